// round 8
// baseline (speedup 1.0000x reference)
#include <cuda_runtime.h>
#include <cuda_fp16.h>
#include <cstdint>

constexpr int kD = 512, kInner = 512, kVocab = 2048;
constexpr int kEncRows = 1024, kDecRows = 256, kMRows = 65536;

__device__ float g_eproj2[2][kEncRows * kInner];   // K-split halves of enc @ We (+b1 in half 0)
__device__ float g_dproj2[2][kDecRows * kInner];   // K-split halves of dec @ Wd
__device__ __half g_w2h[(size_t)kVocab * kInner];  // W2^T as fp16, [v][k]

// ---------------- helpers ----------------
__device__ __forceinline__ uint32_t smem_u32(const void* p) {
    uint32_t a;
    asm("{ .reg .u64 t; cvta.to.shared.u64 t, %1; cvt.u32.u64 %0, t; }" : "=r"(a) : "l"(p));
    return a;
}
#define CP_COMMIT() asm volatile("cp.async.commit_group;" ::: "memory")
#define CP_WAIT0()  asm volatile("cp.async.wait_group 0;" ::: "memory")
__device__ __forceinline__ void cpasync16(uint32_t dst, const void* src) {
    asm volatile("cp.async.cg.shared.global [%0], [%1], 16;" :: "r"(dst), "l"(src) : "memory");
}
#define LDSM_X4(r0, r1, r2, r3, a) \
    asm volatile("ldmatrix.sync.aligned.m8n8.x4.shared.b16 {%0,%1,%2,%3}, [%4];" \
                 : "=r"(r0), "=r"(r1), "=r"(r2), "=r"(r3) : "r"(a))
__device__ __forceinline__ void mma16816(float* c, const uint32_t* a, const uint32_t* b) {
    asm volatile("mma.sync.aligned.m16n8k16.row.col.f32.f16.f16.f32 "
                 "{%0,%1,%2,%3}, {%4,%5,%6,%7}, {%8,%9}, {%0,%1,%2,%3};"
                 : "+f"(c[0]), "+f"(c[1]), "+f"(c[2]), "+f"(c[3])
                 : "r"(a[0]), "r"(a[1]), "r"(a[2]), "r"(a[3]), "r"(b[0]), "r"(b[1]));
}
__device__ __forceinline__ void sts128(uint32_t a, uint32_t x, uint32_t y, uint32_t z, uint32_t w) {
    asm volatile("st.shared.v4.b32 [%0], {%1,%2,%3,%4};" :: "r"(a), "r"(x), "r"(y), "r"(z), "r"(w) : "memory");
}
// proven tanh (same formulation that measured rel_err 2.854e-4)
__device__ __forceinline__ float fast_tanh(float x) {
    float e = __expf(2.0f * x);
    return 1.0f - __fdividef(2.0f, e + 1.0f);
}
__device__ __forceinline__ uint32_t pack_h2(float lo, float hi) {
    uint32_t r;
    asm("cvt.rn.f16x2.f32 %0, %1, %2;" : "=r"(r) : "f"(hi), "f"(lo));
    return r;
}

// ---------------- K1: prep = proj (K-split x2, 640 blocks) + w2h (1024 blocks) --
__global__ void prep_kernel(const float* __restrict__ enc, const float* __restrict__ dec,
                            const float* __restrict__ W1, const float* __restrict__ b1,
                            const float* __restrict__ W2)
{
    const int bid = blockIdx.x;
    const int tid = threadIdx.x;
    if (bid < 1024) {
        // ---- w2h: transpose W2 -> fp16 [v][k] ----
        __shared__ float tile[32][33];
        const int tx = tid & 31, ty = tid >> 5;
        const int v0 = (bid & 63) * 32, k0 = (bid >> 6) * 32;
#pragma unroll
        for (int i = 0; i < 4; i++)
            tile[ty + i * 8][tx] = W2[(size_t)(k0 + ty + i * 8) * kVocab + v0 + tx];
        __syncthreads();
#pragma unroll
        for (int i = 0; i < 4; i++)
            g_w2h[(size_t)(v0 + ty + i * 8) * kInner + k0 + tx] = __float2half_rn(tile[tx][ty + i * 8]);
        return;
    }
    // ---- proj: 32x64 tile, K-split half of 256 (16 k-stages of 16) ----
    __shared__ float As[16][34];
    __shared__ float Ws[16][64];
    const int bid2 = bid - 1024;
    const int bm = bid2 >> 4;
    const int bn = (bid2 & 15) >> 1;
    const int half = bid2 & 1;
    const int row0 = bm * 32;
    const bool is_enc = row0 < kEncRows;
    const float* in = (is_enc ? (enc + row0 * kD) : (dec + (row0 - kEncRows) * kD)) + half * 256;
    const float* W  = (is_enc ? W1 : (W1 + kD * kInner)) + (size_t)half * 256 * kInner;
    const int tx = tid & 15, ty = tid >> 4;

    float acc[2][4];
#pragma unroll
    for (int i = 0; i < 2; i++)
#pragma unroll
        for (int j = 0; j < 4; j++) acc[i][j] = 0.f;

    for (int kt = 0; kt < 16; kt++) {   // FIX: 256 K-values per half = 16 stages
        float2 av = *(const float2*)(in + (tid >> 3) * kD + kt * 16 + (tid & 7) * 2);
        float4 wv = *(const float4*)(W + (kt * 16 + (tid >> 4)) * kInner + bn * 64 + (tid & 15) * 4);
        As[(tid & 7) * 2 + 0][tid >> 3] = av.x;
        As[(tid & 7) * 2 + 1][tid >> 3] = av.y;
        *(float4*)&Ws[tid >> 4][(tid & 15) * 4] = wv;
        __syncthreads();
#pragma unroll
        for (int k = 0; k < 16; k++) {
            float ar[2], br[4];
#pragma unroll
            for (int i = 0; i < 2; i++) ar[i] = As[k][ty * 2 + i];
#pragma unroll
            for (int j = 0; j < 4; j++) br[j] = Ws[k][tx * 4 + j];
#pragma unroll
            for (int i = 0; i < 2; i++)
#pragma unroll
                for (int j = 0; j < 4; j++) acc[i][j] += ar[i] * br[j];
        }
        __syncthreads();
    }
    float* outp = is_enc ? g_eproj2[half] : g_dproj2[half];
    const int obase = is_enc ? row0 : (row0 - kEncRows);
#pragma unroll
    for (int i = 0; i < 2; i++)
#pragma unroll
        for (int j = 0; j < 4; j++) {
            const int n = bn * 64 + tx * 4 + j;
            float v = acc[i][j];
            if (is_enc && half == 0) v += b1[n];
            outp[(obase + ty * 2 + i) * kInner + n] = v;
        }
}

// ---------------- K3: fused tanh + fp16 mma GEMM, persistent A, 8 warps -------
// BM=128 (full K=512 A resident, 128KB), BN=256, BK=64 double-buffered B.
// 256 threads, 8 warps (2x4), warp tile 64x64.
constexpr int SMA = 0;              // A: 8 x 128 x 128B = 128KB
constexpr int SMB = 131072;         // B: 2 x 256 x 128B = 64KB
constexpr int SMEM_TOTAL = 196608;  // 192KB

__global__ __launch_bounds__(256, 1)
void fused_joint_kernel(const float* __restrict__ b2, float* __restrict__ out)
{
    extern __shared__ char smem[];
    const uint32_t sb = smem_u32(smem);
    const int tid = threadIdx.x;
    const int lane = tid & 31, wid = tid >> 5;
    const int wm = wid >> 2, wn = wid & 3;
    const int bmp = blockIdx.x;

    // A producer mapping: 2 threads/row, 32 k-elems each
    const int arow = tid >> 1, apart = tid & 1;
    const int gm = bmp * 128 + arow;
    const size_t eoff = (size_t)(gm >> 6) * kInner + apart * 32;
    const size_t doff = (size_t)(((gm >> 14) << 6) | (gm & 63)) * kInner + apart * 32;
    const float* e0p = g_eproj2[0] + eoff;
    const float* e1p = g_eproj2[1] + eoff;
    const float* d0p = g_dproj2[0] + doff;
    const float* d1p = g_dproj2[1] + doff;
    const uint32_t a_sts = sb + SMA + arow * 128;
    const int ar7 = arow & 7;
    // B producer mapping: 1 thread/row, 8 x 16B chunks
    const __half* wp = g_w2h + (size_t)tid * kInner;
    const uint32_t b_sts = sb + SMB + tid * 128;
    const int t7 = tid & 7;

#define PRODUCE_B(s, buf) do { \
    const __half* wps_ = wp + (size_t)((s) >> 3) * 256 * kInner + ((s) & 7) * 64; \
    const uint32_t bb_ = b_sts + (buf) * 32768; \
    _Pragma("unroll") \
    for (int j = 0; j < 8; j++) \
        cpasync16(bb_ + ((j ^ t7) * 16), wps_ + j * 8); \
    } while (0)

    // ---- prologue: stage-0 B load overlapped with full-A tanh production ----
    PRODUCE_B(0, 0);
    CP_COMMIT();
#pragma unroll 1
    for (int kt = 0; kt < 8; kt++) {
        const uint32_t ab_ = a_sts + kt * 16384;
        const int kb = kt * 64;
#pragma unroll
        for (int j = 0; j < 4; j++) {
            const int k = kb + j * 8;
            float4 ea0 = *(const float4*)(e0p + k);
            float4 eb0 = *(const float4*)(e1p + k);
            float4 da0 = *(const float4*)(d0p + k);
            float4 db0 = *(const float4*)(d1p + k);
            float4 ea1 = *(const float4*)(e0p + k + 4);
            float4 eb1 = *(const float4*)(e1p + k + 4);
            float4 da1 = *(const float4*)(d0p + k + 4);
            float4 db1 = *(const float4*)(d1p + k + 4);
            uint32_t h0 = pack_h2(fast_tanh(ea0.x + eb0.x + da0.x + db0.x),
                                  fast_tanh(ea0.y + eb0.y + da0.y + db0.y));
            uint32_t h1 = pack_h2(fast_tanh(ea0.z + eb0.z + da0.z + db0.z),
                                  fast_tanh(ea0.w + eb0.w + da0.w + db0.w));
            uint32_t h2 = pack_h2(fast_tanh(ea1.x + eb1.x + da1.x + db1.x),
                                  fast_tanh(ea1.y + eb1.y + da1.y + db1.y));
            uint32_t h3 = pack_h2(fast_tanh(ea1.z + eb1.z + da1.z + db1.z),
                                  fast_tanh(ea1.w + eb1.w + da1.w + db1.w));
            const int c_ = apart * 4 + j;
            sts128(ab_ + ((c_ ^ ar7) * 16), h0, h1, h2, h3);
        }
    }
    CP_WAIT0();
    __syncthreads();

    float acc[4][8][4];
#pragma unroll
    for (int mt = 0; mt < 4; mt++)
#pragma unroll
        for (int nt = 0; nt < 8; nt++)
#pragma unroll
            for (int i = 0; i < 4; i++) acc[mt][nt][i] = 0.f;

    const int rbase = bmp * 128 + wm * 64;
    const int g2 = lane >> 2, l2 = lane & 3;

    // ---- mainloop: 64 stages = 8 bn tiles x 8 k-stages ----
#pragma unroll 1
    for (int s = 0; s < 64; s++) {
        const int buf = s & 1;
        if (s < 63) PRODUCE_B(s + 1, buf ^ 1);
        CP_COMMIT();
        const uint32_t Ab = sb + SMA + (s & 7) * 16384;
        const uint32_t Bb = sb + SMB + buf * 32768;
#pragma unroll
        for (int kc = 0; kc < 4; kc++) {
            uint32_t afr[4][4], bfr[8][2];
#pragma unroll
            for (int mt = 0; mt < 4; mt++) {
                const int row = wm * 64 + mt * 16 + (lane & 15);
                const int ch = (kc * 2 + (lane >> 4)) ^ (lane & 7);
                LDSM_X4(afr[mt][0], afr[mt][1], afr[mt][2], afr[mt][3],
                        Ab + row * 128 + ch * 16);
            }
#pragma unroll
            for (int np = 0; np < 4; np++) {
                const int n = wn * 64 + np * 16 + (lane & 7) + ((lane >> 4) << 3);
                const int ch = (kc * 2 + ((lane >> 3) & 1)) ^ (lane & 7);
                LDSM_X4(bfr[np * 2][0], bfr[np * 2][1], bfr[np * 2 + 1][0], bfr[np * 2 + 1][1],
                        Bb + n * 128 + ch * 16);
            }
#pragma unroll
            for (int mt = 0; mt < 4; mt++)
#pragma unroll
                for (int nt = 0; nt < 8; nt++)
                    mma16816(acc[mt][nt], afr[mt], bfr[nt]);
        }
        if ((s & 7) == 7) {
            // finished bn tile: add b2, write out, reset acc
            const int bn = s >> 3;
            const int cbase = bn * 256 + wn * 64;
#pragma unroll
            for (int nt = 0; nt < 8; nt++) {
                const int c0 = cbase + nt * 8 + l2 * 2;
                const float2 bb = *(const float2*)(b2 + c0);
#pragma unroll
                for (int mt = 0; mt < 4; mt++) {
                    const int r0 = rbase + mt * 16 + g2;
                    float2 v0 = make_float2(acc[mt][nt][0] + bb.x, acc[mt][nt][1] + bb.y);
                    float2 v1 = make_float2(acc[mt][nt][2] + bb.x, acc[mt][nt][3] + bb.y);
                    *(float2*)(out + (size_t)r0 * kVocab + c0) = v0;
                    *(float2*)(out + (size_t)(r0 + 8) * kVocab + c0) = v1;
#pragma unroll
                    for (int i = 0; i < 4; i++) acc[mt][nt][i] = 0.f;
                }
            }
        }
        CP_WAIT0();
        __syncthreads();
    }
}

// ---------------------------------------------------------------------------
extern "C" void kernel_launch(void* const* d_in, const int* in_sizes, int n_in,
                              void* d_out, int out_size)
{
    const float* enc = (const float*)d_in[0];
    const float* dec = (const float*)d_in[1];
    const float* W1  = (const float*)d_in[2];
    const float* b1  = (const float*)d_in[3];
    const float* W2  = (const float*)d_in[4];
    const float* b2  = (const float*)d_in[5];
    float* out = (float*)d_out;

    cudaFuncSetAttribute(fused_joint_kernel,
                         cudaFuncAttributeMaxDynamicSharedMemorySize, SMEM_TOTAL);

    prep_kernel<<<1024 + 640, 256>>>(enc, dec, W1, b1, W2);
    fused_joint_kernel<<<kMRows / 128, 256, SMEM_TOTAL>>>(b2, out);
}

// round 10
// speedup vs baseline: 1.2261x; 1.2261x over previous
#include <cuda_runtime.h>
#include <cuda_fp16.h>
#include <cstdint>

constexpr int kD = 512, kInner = 512, kVocab = 2048;
constexpr int kEncRows = 1024, kDecRows = 256, kMRows = 65536;

__device__ float g_eproj2[2][kEncRows * kInner];   // K-split halves of enc @ We (+b1 in half 0)
__device__ float g_dproj2[2][kDecRows * kInner];   // K-split halves of dec @ Wd
__device__ __half g_w2h[(size_t)kVocab * kInner];  // W2^T as fp16, [v][k]

// ---------------- helpers ----------------
__device__ __forceinline__ uint32_t smem_u32(const void* p) {
    uint32_t a;
    asm("{ .reg .u64 t; cvta.to.shared.u64 t, %1; cvt.u32.u64 %0, t; }" : "=r"(a) : "l"(p));
    return a;
}
#define CP_COMMIT() asm volatile("cp.async.commit_group;" ::: "memory")
#define CP_WAIT0()  asm volatile("cp.async.wait_group 0;" ::: "memory")
#define CP_WAIT1()  asm volatile("cp.async.wait_group 1;" ::: "memory")
__device__ __forceinline__ void cpasync16(uint32_t dst, const void* src) {
    asm volatile("cp.async.cg.shared.global [%0], [%1], 16;" :: "r"(dst), "l"(src) : "memory");
}
#define LDSM_X4(r0, r1, r2, r3, a) \
    asm volatile("ldmatrix.sync.aligned.m8n8.x4.shared.b16 {%0,%1,%2,%3}, [%4];" \
                 : "=r"(r0), "=r"(r1), "=r"(r2), "=r"(r3) : "r"(a))
__device__ __forceinline__ void mma16816(float* c, const uint32_t* a, const uint32_t* b) {
    asm volatile("mma.sync.aligned.m16n8k16.row.col.f32.f16.f16.f32 "
                 "{%0,%1,%2,%3}, {%4,%5,%6,%7}, {%8,%9}, {%0,%1,%2,%3};"
                 : "+f"(c[0]), "+f"(c[1]), "+f"(c[2]), "+f"(c[3])
                 : "r"(a[0]), "r"(a[1]), "r"(a[2]), "r"(a[3]), "r"(b[0]), "r"(b[1]));
}
__device__ __forceinline__ void sts128(uint32_t a, uint32_t x, uint32_t y, uint32_t z, uint32_t w) {
    asm volatile("st.shared.v4.b32 [%0], {%1,%2,%3,%4};" :: "r"(a), "r"(x), "r"(y), "r"(z), "r"(w) : "memory");
}
// proven tanh (same formulation that measured rel_err 2.854e-4)
__device__ __forceinline__ float fast_tanh(float x) {
    float e = __expf(2.0f * x);
    return 1.0f - __fdividef(2.0f, e + 1.0f);
}
__device__ __forceinline__ uint32_t pack_h2(float lo, float hi) {
    uint32_t r;
    asm("cvt.rn.f16x2.f32 %0, %1, %2;" : "=r"(r) : "f"(hi), "f"(lo));
    return r;
}

// ---------------- K1: prep = proj (K-split x2, 640 blocks) + w2h (1024 blocks) --
__global__ void prep_kernel(const float* __restrict__ enc, const float* __restrict__ dec,
                            const float* __restrict__ W1, const float* __restrict__ b1,
                            const float* __restrict__ W2)
{
    const int bid = blockIdx.x;
    const int tid = threadIdx.x;
    if (bid < 1024) {
        // ---- w2h: transpose W2 -> fp16 [v][k] ----
        __shared__ float tile[32][33];
        const int tx = tid & 31, ty = tid >> 5;
        const int v0 = (bid & 63) * 32, k0 = (bid >> 6) * 32;
#pragma unroll
        for (int i = 0; i < 4; i++)
            tile[ty + i * 8][tx] = W2[(size_t)(k0 + ty + i * 8) * kVocab + v0 + tx];
        __syncthreads();
#pragma unroll
        for (int i = 0; i < 4; i++)
            g_w2h[(size_t)(v0 + ty + i * 8) * kInner + k0 + tx] = __float2half_rn(tile[tx][ty + i * 8]);
        return;
    }
    // ---- proj: 32x64 tile, K-split half of 256 (16 k-stages of 16) ----
    __shared__ float As[16][34];
    __shared__ float Ws[16][64];
    const int bid2 = bid - 1024;
    const int bm = bid2 >> 4;
    const int bn = (bid2 & 15) >> 1;
    const int half = bid2 & 1;
    const int row0 = bm * 32;
    const bool is_enc = row0 < kEncRows;
    const float* in = (is_enc ? (enc + row0 * kD) : (dec + (row0 - kEncRows) * kD)) + half * 256;
    const float* W  = (is_enc ? W1 : (W1 + kD * kInner)) + (size_t)half * 256 * kInner;
    const int tx = tid & 15, ty = tid >> 4;

    float acc[2][4];
#pragma unroll
    for (int i = 0; i < 2; i++)
#pragma unroll
        for (int j = 0; j < 4; j++) acc[i][j] = 0.f;

    for (int kt = 0; kt < 16; kt++) {
        float2 av = *(const float2*)(in + (tid >> 3) * kD + kt * 16 + (tid & 7) * 2);
        float4 wv = *(const float4*)(W + (kt * 16 + (tid >> 4)) * kInner + bn * 64 + (tid & 15) * 4);
        As[(tid & 7) * 2 + 0][tid >> 3] = av.x;
        As[(tid & 7) * 2 + 1][tid >> 3] = av.y;
        *(float4*)&Ws[tid >> 4][(tid & 15) * 4] = wv;
        __syncthreads();
#pragma unroll
        for (int k = 0; k < 16; k++) {
            float ar[2], br[4];
#pragma unroll
            for (int i = 0; i < 2; i++) ar[i] = As[k][ty * 2 + i];
#pragma unroll
            for (int j = 0; j < 4; j++) br[j] = Ws[k][tx * 4 + j];
#pragma unroll
            for (int i = 0; i < 2; i++)
#pragma unroll
                for (int j = 0; j < 4; j++) acc[i][j] += ar[i] * br[j];
        }
        __syncthreads();
    }
    float* outp = is_enc ? g_eproj2[half] : g_dproj2[half];
    const int obase = is_enc ? row0 : (row0 - kEncRows);
#pragma unroll
    for (int i = 0; i < 2; i++)
#pragma unroll
        for (int j = 0; j < 4; j++) {
            const int n = bn * 64 + tx * 4 + j;
            float v = acc[i][j];
            if (is_enc && half == 0) v += b1[n];
            outp[(obase + ty * 2 + i) * kInner + n] = v;
        }
}

// ---------------- K3: fused tanh + fp16 mma GEMM, persistent A, 16 warps ------
// BM=128 (full K=512 A resident, 128KB), BN=256, BK=64, 3-stage B ring.
// 512 threads, 16 warps (2x8), warp tile 64x32.
constexpr int SMA = 0;                       // A: 8 x 128 x 128B = 128KB
constexpr int SMB = 131072;                  // B: 3 x 256 x 128B = 96KB
constexpr int SMEM_TOTAL = 131072 + 98304;   // 224KB

__global__ __launch_bounds__(512, 1)
void fused_joint_kernel(const float* __restrict__ b2, float* __restrict__ out)
{
    extern __shared__ char smem[];
    const uint32_t sb = smem_u32(smem);
    const int tid = threadIdx.x;
    const int lane = tid & 31, wid = tid >> 5;
    const int wm = wid >> 3, wn = wid & 7;
    const int bmp = blockIdx.x;

    // A producer mapping: 4 threads/row, 16 k-elems each
    const int arow = tid >> 2, apart = tid & 3;
    const int gm = bmp * 128 + arow;
    const size_t eoff = (size_t)(gm >> 6) * kInner + apart * 16;
    const size_t doff = (size_t)(((gm >> 14) << 6) | (gm & 63)) * kInner + apart * 16;
    const float* e0p = g_eproj2[0] + eoff;
    const float* e1p = g_eproj2[1] + eoff;
    const float* d0p = g_dproj2[0] + doff;
    const float* d1p = g_dproj2[1] + doff;
    const uint32_t a_sts = sb + SMA + arow * 128;
    const int ar7 = arow & 7;
    // B producer mapping: 2 threads/row, 4 x 16B chunks each
    const int brow = tid >> 1;
    const __half* wp = g_w2h + (size_t)brow * kInner + (tid & 1) * 32;
    const uint32_t b_sts = sb + SMB + brow * 128;
    const int br7 = brow & 7;

#define PRODUCE_B(s, buf) do { \
    const __half* wps_ = wp + (size_t)((s) >> 3) * 256 * kInner + ((s) & 7) * 64; \
    const uint32_t bb_ = b_sts + (buf) * 32768; \
    _Pragma("unroll") \
    for (int j = 0; j < 4; j++) { \
        const int c_ = (tid & 1) * 4 + j; \
        cpasync16(bb_ + ((c_ ^ br7) * 16), wps_ + j * 8); \
    } } while (0)

    // ---- prologue: stage 0+1 B loads overlapped with full-A tanh production ----
    PRODUCE_B(0, 0);
    CP_COMMIT();
    PRODUCE_B(1, 1);
    CP_COMMIT();
#pragma unroll 1
    for (int kt = 0; kt < 8; kt++) {
        const uint32_t ab_ = a_sts + kt * 16384;
#pragma unroll
        for (int j = 0; j < 2; j++) {
            const int k = kt * 64 + j * 8;
            float4 ea0 = *(const float4*)(e0p + k);
            float4 eb0 = *(const float4*)(e1p + k);
            float4 da0 = *(const float4*)(d0p + k);
            float4 db0 = *(const float4*)(d1p + k);
            float4 ea1 = *(const float4*)(e0p + k + 4);
            float4 eb1 = *(const float4*)(e1p + k + 4);
            float4 da1 = *(const float4*)(d0p + k + 4);
            float4 db1 = *(const float4*)(d1p + k + 4);
            uint32_t h0 = pack_h2(fast_tanh(ea0.x + eb0.x + da0.x + db0.x),
                                  fast_tanh(ea0.y + eb0.y + da0.y + db0.y));
            uint32_t h1 = pack_h2(fast_tanh(ea0.z + eb0.z + da0.z + db0.z),
                                  fast_tanh(ea0.w + eb0.w + da0.w + db0.w));
            uint32_t h2 = pack_h2(fast_tanh(ea1.x + eb1.x + da1.x + db1.x),
                                  fast_tanh(ea1.y + eb1.y + da1.y + db1.y));
            uint32_t h3 = pack_h2(fast_tanh(ea1.z + eb1.z + da1.z + db1.z),
                                  fast_tanh(ea1.w + eb1.w + da1.w + db1.w));
            const int c_ = apart * 2 + j;
            sts128(ab_ + ((c_ ^ ar7) * 16), h0, h1, h2, h3);
        }
    }
    CP_WAIT1();   // stage 0 landed
    __syncthreads();

    float acc[4][4][4];
#pragma unroll
    for (int mt = 0; mt < 4; mt++)
#pragma unroll
        for (int nt = 0; nt < 4; nt++)
#pragma unroll
            for (int i = 0; i < 4; i++) acc[mt][nt][i] = 0.f;

    const int rbase = bmp * 128 + wm * 64;
    const int g2 = lane >> 2, l2 = lane & 3;

    // ---- mainloop: 64 stages = 8 bn tiles x 8 k-stages, 3-stage B ring ----
    int buf = 0, pbuf = 2;
#pragma unroll 1
    for (int s = 0; s < 64; s++) {
        if (s < 62) {
            PRODUCE_B(s + 2, pbuf);
            CP_COMMIT();
            pbuf = (pbuf == 2) ? 0 : pbuf + 1;
        }
        const uint32_t Ab = sb + SMA + (s & 7) * 16384;
        const uint32_t Bb = sb + SMB + buf * 32768;
#pragma unroll
        for (int kc = 0; kc < 4; kc++) {
            uint32_t afr[4][4], bfr[4][2];
#pragma unroll
            for (int mt = 0; mt < 4; mt++) {
                const int row = wm * 64 + mt * 16 + (lane & 15);
                const int ch = (kc * 2 + (lane >> 4)) ^ (lane & 7);
                LDSM_X4(afr[mt][0], afr[mt][1], afr[mt][2], afr[mt][3],
                        Ab + row * 128 + ch * 16);
            }
#pragma unroll
            for (int np = 0; np < 2; np++) {
                const int n = wn * 32 + np * 16 + (lane & 7) + ((lane >> 4) << 3);
                const int ch = (kc * 2 + ((lane >> 3) & 1)) ^ (lane & 7);
                LDSM_X4(bfr[np * 2][0], bfr[np * 2][1], bfr[np * 2 + 1][0], bfr[np * 2 + 1][1],
                        Bb + n * 128 + ch * 16);
            }
#pragma unroll
            for (int mt = 0; mt < 4; mt++)
#pragma unroll
                for (int nt = 0; nt < 4; nt++)
                    mma16816(acc[mt][nt], afr[mt], bfr[nt]);
        }
        if ((s & 7) == 7) {
            // finished bn tile: add b2, write out, reset acc
            const int bn = s >> 3;
            const int cbase = bn * 256 + wn * 32;
#pragma unroll
            for (int nt = 0; nt < 4; nt++) {
                const int c0 = cbase + nt * 8 + l2 * 2;
                const float2 bb = *(const float2*)(b2 + c0);
#pragma unroll
                for (int mt = 0; mt < 4; mt++) {
                    const int r0 = rbase + mt * 16 + g2;
                    float2 v0 = make_float2(acc[mt][nt][0] + bb.x, acc[mt][nt][1] + bb.y);
                    float2 v1 = make_float2(acc[mt][nt][2] + bb.x, acc[mt][nt][3] + bb.y);
                    *(float2*)(out + (size_t)r0 * kVocab + c0) = v0;
                    *(float2*)(out + (size_t)(r0 + 8) * kVocab + c0) = v1;
#pragma unroll
                    for (int i = 0; i < 4; i++) acc[mt][nt][i] = 0.f;
                }
            }
        }
        buf = (buf == 2) ? 0 : buf + 1;
        if (s < 62) CP_WAIT1();
        else        CP_WAIT0();
        __syncthreads();
    }
}

// ---------------------------------------------------------------------------
extern "C" void kernel_launch(void* const* d_in, const int* in_sizes, int n_in,
                              void* d_out, int out_size)
{
    const float* enc = (const float*)d_in[0];
    const float* dec = (const float*)d_in[1];
    const float* W1  = (const float*)d_in[2];
    const float* b1  = (const float*)d_in[3];
    const float* W2  = (const float*)d_in[4];
    const float* b2  = (const float*)d_in[5];
    float* out = (float*)d_out;

    cudaFuncSetAttribute(fused_joint_kernel,
                         cudaFuncAttributeMaxDynamicSharedMemorySize, SMEM_TOTAL);

    prep_kernel<<<1024 + 640, 256>>>(enc, dec, W1, b1, W2);
    fused_joint_kernel<<<kMRows / 128, 512, SMEM_TOTAL>>>(b2, out);
}

// round 11
// speedup vs baseline: 1.2427x; 1.0135x over previous
#include <cuda_runtime.h>
#include <cuda_fp16.h>
#include <cstdint>

constexpr int kD = 512, kInner = 512, kVocab = 2048;
constexpr int kEncRows = 1024, kDecRows = 256, kMRows = 65536;

__device__ float g_eproj2[2][kEncRows * kInner];   // K-split halves of enc @ We (+b1 in half 0)
__device__ float g_dproj2[2][kDecRows * kInner];   // K-split halves of dec @ Wd
__device__ __half g_w2h[(size_t)kVocab * kInner];  // W2^T as fp16, [v][k]

// ---------------- helpers ----------------
__device__ __forceinline__ uint32_t smem_u32(const void* p) {
    uint32_t a;
    asm("{ .reg .u64 t; cvta.to.shared.u64 t, %1; cvt.u32.u64 %0, t; }" : "=r"(a) : "l"(p));
    return a;
}
#define CP_COMMIT() asm volatile("cp.async.commit_group;" ::: "memory")
#define CP_WAIT0()  asm volatile("cp.async.wait_group 0;" ::: "memory")
__device__ __forceinline__ void cpasync16(uint32_t dst, const void* src) {
    asm volatile("cp.async.cg.shared.global [%0], [%1], 16;" :: "r"(dst), "l"(src) : "memory");
}
#define LDSM_X4(r0, r1, r2, r3, a) \
    asm volatile("ldmatrix.sync.aligned.m8n8.x4.shared.b16 {%0,%1,%2,%3}, [%4];" \
                 : "=r"(r0), "=r"(r1), "=r"(r2), "=r"(r3) : "r"(a))
__device__ __forceinline__ void mma16816(float* c, const uint32_t* a, const uint32_t* b) {
    asm volatile("mma.sync.aligned.m16n8k16.row.col.f32.f16.f16.f32 "
                 "{%0,%1,%2,%3}, {%4,%5,%6,%7}, {%8,%9}, {%0,%1,%2,%3};"
                 : "+f"(c[0]), "+f"(c[1]), "+f"(c[2]), "+f"(c[3])
                 : "r"(a[0]), "r"(a[1]), "r"(a[2]), "r"(a[3]), "r"(b[0]), "r"(b[1]));
}
__device__ __forceinline__ void sts128(uint32_t a, uint32_t x, uint32_t y, uint32_t z, uint32_t w) {
    asm volatile("st.shared.v4.b32 [%0], {%1,%2,%3,%4};" :: "r"(a), "r"(x), "r"(y), "r"(z), "r"(w) : "memory");
}
// proven tanh (same formulation that measured rel_err 2.854e-4)
__device__ __forceinline__ float fast_tanh(float x) {
    float e = __expf(2.0f * x);
    return 1.0f - __fdividef(2.0f, e + 1.0f);
}
__device__ __forceinline__ uint32_t pack_h2(float lo, float hi) {
    uint32_t r;
    asm("cvt.rn.f16x2.f32 %0, %1, %2;" : "=r"(r) : "f"(hi), "f"(lo));
    return r;
}

// ---------------- K1: prep = proj (K-split x2, 640 blocks) + w2h (1024 blocks) --
__global__ void prep_kernel(const float* __restrict__ enc, const float* __restrict__ dec,
                            const float* __restrict__ W1, const float* __restrict__ b1,
                            const float* __restrict__ W2)
{
    const int bid = blockIdx.x;
    const int tid = threadIdx.x;
    if (bid < 1024) {
        // ---- w2h: transpose W2 -> fp16 [v][k] ----
        __shared__ float tile[32][33];
        const int tx = tid & 31, ty = tid >> 5;
        const int v0 = (bid & 63) * 32, k0 = (bid >> 6) * 32;
#pragma unroll
        for (int i = 0; i < 4; i++)
            tile[ty + i * 8][tx] = W2[(size_t)(k0 + ty + i * 8) * kVocab + v0 + tx];
        __syncthreads();
#pragma unroll
        for (int i = 0; i < 4; i++)
            g_w2h[(size_t)(v0 + ty + i * 8) * kInner + k0 + tx] = __float2half_rn(tile[tx][ty + i * 8]);
        return;
    }
    // ---- proj: 32x64 tile, K-split half of 256 (16 k-stages of 16) ----
    __shared__ float As[16][34];
    __shared__ float Ws[16][64];
    const int bid2 = bid - 1024;
    const int bm = bid2 >> 4;
    const int bn = (bid2 & 15) >> 1;
    const int half = bid2 & 1;
    const int row0 = bm * 32;
    const bool is_enc = row0 < kEncRows;
    const float* in = (is_enc ? (enc + row0 * kD) : (dec + (row0 - kEncRows) * kD)) + half * 256;
    const float* W  = (is_enc ? W1 : (W1 + kD * kInner)) + (size_t)half * 256 * kInner;
    const int tx = tid & 15, ty = tid >> 4;

    float acc[2][4];
#pragma unroll
    for (int i = 0; i < 2; i++)
#pragma unroll
        for (int j = 0; j < 4; j++) acc[i][j] = 0.f;

    for (int kt = 0; kt < 16; kt++) {
        float2 av = *(const float2*)(in + (tid >> 3) * kD + kt * 16 + (tid & 7) * 2);
        float4 wv = *(const float4*)(W + (kt * 16 + (tid >> 4)) * kInner + bn * 64 + (tid & 15) * 4);
        As[(tid & 7) * 2 + 0][tid >> 3] = av.x;
        As[(tid & 7) * 2 + 1][tid >> 3] = av.y;
        *(float4*)&Ws[tid >> 4][(tid & 15) * 4] = wv;
        __syncthreads();
#pragma unroll
        for (int k = 0; k < 16; k++) {
            float ar[2], br[4];
#pragma unroll
            for (int i = 0; i < 2; i++) ar[i] = As[k][ty * 2 + i];
#pragma unroll
            for (int j = 0; j < 4; j++) br[j] = Ws[k][tx * 4 + j];
#pragma unroll
            for (int i = 0; i < 2; i++)
#pragma unroll
                for (int j = 0; j < 4; j++) acc[i][j] += ar[i] * br[j];
        }
        __syncthreads();
    }
    float* outp = is_enc ? g_eproj2[half] : g_dproj2[half];
    const int obase = is_enc ? row0 : (row0 - kEncRows);
#pragma unroll
    for (int i = 0; i < 2; i++)
#pragma unroll
        for (int j = 0; j < 4; j++) {
            const int n = bn * 64 + tx * 4 + j;
            float v = acc[i][j];
            if (is_enc && half == 0) v += b1[n];
            outp[(obase + ty * 2 + i) * kInner + n] = v;
        }
}

// ---------------- K3: fused tanh + fp16 mma GEMM, persistent A, 16 warps ------
// BM=128 (full K=512 A resident, 128KB), BN=256, BK=64, 2-stage B (R6-proven).
// 512 threads, 16 warps (2x8), warp tile 64x32.
// NEW: register-level fragment double-buffering across kc iterations.
constexpr int SMA = 0;              // A: 8 x 128 x 128B = 128KB
constexpr int SMB = 131072;         // B: 2 x 256 x 128B = 64KB
constexpr int SMEM_TOTAL = 196608;  // 192KB

__global__ __launch_bounds__(512, 1)
void fused_joint_kernel(const float* __restrict__ b2, float* __restrict__ out)
{
    extern __shared__ char smem[];
    const uint32_t sb = smem_u32(smem);
    const int tid = threadIdx.x;
    const int lane = tid & 31, wid = tid >> 5;
    const int wm = wid >> 3, wn = wid & 7;
    const int bmp = blockIdx.x;

    // A producer mapping: 4 threads/row, 16 k-elems each
    const int arow = tid >> 2, apart = tid & 3;
    const int gm = bmp * 128 + arow;
    const size_t eoff = (size_t)(gm >> 6) * kInner + apart * 16;
    const size_t doff = (size_t)(((gm >> 14) << 6) | (gm & 63)) * kInner + apart * 16;
    const float* e0p = g_eproj2[0] + eoff;
    const float* e1p = g_eproj2[1] + eoff;
    const float* d0p = g_dproj2[0] + doff;
    const float* d1p = g_dproj2[1] + doff;
    const uint32_t a_sts = sb + SMA + arow * 128;
    const int ar7 = arow & 7;
    // B producer mapping: 2 threads/row, 4 x 16B chunks each
    const int brow = tid >> 1;
    const __half* wp = g_w2h + (size_t)brow * kInner + (tid & 1) * 32;
    const uint32_t b_sts = sb + SMB + brow * 128;
    const int br7 = brow & 7;

#define PRODUCE_B(s, buf) do { \
    const __half* wps_ = wp + (size_t)((s) >> 3) * 256 * kInner + ((s) & 7) * 64; \
    const uint32_t bb_ = b_sts + (buf) * 32768; \
    _Pragma("unroll") \
    for (int j = 0; j < 4; j++) { \
        const int c_ = (tid & 1) * 4 + j; \
        cpasync16(bb_ + ((c_ ^ br7) * 16), wps_ + j * 8); \
    } } while (0)

    // ---- prologue: stage-0 B load overlapped with full-A tanh production ----
    PRODUCE_B(0, 0);
    CP_COMMIT();
#pragma unroll 1
    for (int kt = 0; kt < 8; kt++) {
        const uint32_t ab_ = a_sts + kt * 16384;
#pragma unroll
        for (int j = 0; j < 2; j++) {
            const int k = kt * 64 + j * 8;
            float4 ea0 = *(const float4*)(e0p + k);
            float4 eb0 = *(const float4*)(e1p + k);
            float4 da0 = *(const float4*)(d0p + k);
            float4 db0 = *(const float4*)(d1p + k);
            float4 ea1 = *(const float4*)(e0p + k + 4);
            float4 eb1 = *(const float4*)(e1p + k + 4);
            float4 da1 = *(const float4*)(d0p + k + 4);
            float4 db1 = *(const float4*)(d1p + k + 4);
            uint32_t h0 = pack_h2(fast_tanh(ea0.x + eb0.x + da0.x + db0.x),
                                  fast_tanh(ea0.y + eb0.y + da0.y + db0.y));
            uint32_t h1 = pack_h2(fast_tanh(ea0.z + eb0.z + da0.z + db0.z),
                                  fast_tanh(ea0.w + eb0.w + da0.w + db0.w));
            uint32_t h2 = pack_h2(fast_tanh(ea1.x + eb1.x + da1.x + db1.x),
                                  fast_tanh(ea1.y + eb1.y + da1.y + db1.y));
            uint32_t h3 = pack_h2(fast_tanh(ea1.z + eb1.z + da1.z + db1.z),
                                  fast_tanh(ea1.w + eb1.w + da1.w + db1.w));
            const int c_ = apart * 2 + j;
            sts128(ab_ + ((c_ ^ ar7) * 16), h0, h1, h2, h3);
        }
    }
    CP_WAIT0();
    __syncthreads();

    float acc[4][4][4];
#pragma unroll
    for (int mt = 0; mt < 4; mt++)
#pragma unroll
        for (int nt = 0; nt < 4; nt++)
#pragma unroll
            for (int i = 0; i < 4; i++) acc[mt][nt][i] = 0.f;

    const int rbase = bmp * 128 + wm * 64;
    const int g2 = lane >> 2, l2 = lane & 3;
    // fragment-load address components (constant per thread)
    const int a_rbase = wm * 64 + (lane & 15);       // + mt*16
    const int a_hi = lane >> 4;                      // k-half select
    const int al7 = lane & 7;
    const int b_nbase = wn * 32 + (lane & 7) + ((lane >> 4) << 3);  // + np*16
    const int b_hi = (lane >> 3) & 1;

    // ---- mainloop: 64 stages = 8 bn tiles x 8 k-stages, 2-stage B ----
#pragma unroll 1
    for (int s = 0; s < 64; s++) {
        const int buf = s & 1;
        if (s < 63) PRODUCE_B(s + 1, buf ^ 1);
        CP_COMMIT();
        const uint32_t Ab = sb + SMA + (s & 7) * 16384;
        const uint32_t Bb = sb + SMB + buf * 32768;

        uint32_t afr[2][4][4], bfr[2][4][2];
        // preload kc=0 fragments
#pragma unroll
        for (int mt = 0; mt < 4; mt++) {
            const int ch = a_hi ^ al7;
            LDSM_X4(afr[0][mt][0], afr[0][mt][1], afr[0][mt][2], afr[0][mt][3],
                    Ab + (a_rbase + mt * 16) * 128 + ch * 16);
        }
#pragma unroll
        for (int np = 0; np < 2; np++) {
            const int ch = b_hi ^ al7;
            LDSM_X4(bfr[0][np * 2][0], bfr[0][np * 2][1], bfr[0][np * 2 + 1][0], bfr[0][np * 2 + 1][1],
                    Bb + (b_nbase + np * 16) * 128 + ch * 16);
        }
#pragma unroll
        for (int kc = 0; kc < 4; kc++) {
            const int cur = kc & 1, nxt = cur ^ 1;
            if (kc < 3) {
                // prefetch kc+1 fragments BEFORE issuing kc's MMAs
#pragma unroll
                for (int mt = 0; mt < 4; mt++) {
                    const int ch = ((kc + 1) * 2 + a_hi) ^ al7;
                    LDSM_X4(afr[nxt][mt][0], afr[nxt][mt][1], afr[nxt][mt][2], afr[nxt][mt][3],
                            Ab + (a_rbase + mt * 16) * 128 + ch * 16);
                }
#pragma unroll
                for (int np = 0; np < 2; np++) {
                    const int ch = ((kc + 1) * 2 + b_hi) ^ al7;
                    LDSM_X4(bfr[nxt][np * 2][0], bfr[nxt][np * 2][1],
                            bfr[nxt][np * 2 + 1][0], bfr[nxt][np * 2 + 1][1],
                            Bb + (b_nbase + np * 16) * 128 + ch * 16);
                }
            }
#pragma unroll
            for (int mt = 0; mt < 4; mt++)
#pragma unroll
                for (int nt = 0; nt < 4; nt++)
                    mma16816(acc[mt][nt], afr[cur][mt], bfr[cur][nt]);
        }

        if ((s & 7) == 7) {
            // finished bn tile: add b2, write out, reset acc
            const int bn = s >> 3;
            const int cbase = bn * 256 + wn * 32;
#pragma unroll
            for (int nt = 0; nt < 4; nt++) {
                const int c0 = cbase + nt * 8 + l2 * 2;
                const float2 bb = *(const float2*)(b2 + c0);
#pragma unroll
                for (int mt = 0; mt < 4; mt++) {
                    const int r0 = rbase + mt * 16 + g2;
                    float2 v0 = make_float2(acc[mt][nt][0] + bb.x, acc[mt][nt][1] + bb.y);
                    float2 v1 = make_float2(acc[mt][nt][2] + bb.x, acc[mt][nt][3] + bb.y);
                    *(float2*)(out + (size_t)r0 * kVocab + c0) = v0;
                    *(float2*)(out + (size_t)(r0 + 8) * kVocab + c0) = v1;
#pragma unroll
                    for (int i = 0; i < 4; i++) acc[mt][nt][i] = 0.f;
                }
            }
        }
        CP_WAIT0();
        __syncthreads();
    }
}

// ---------------------------------------------------------------------------
extern "C" void kernel_launch(void* const* d_in, const int* in_sizes, int n_in,
                              void* d_out, int out_size)
{
    const float* enc = (const float*)d_in[0];
    const float* dec = (const float*)d_in[1];
    const float* W1  = (const float*)d_in[2];
    const float* b1  = (const float*)d_in[3];
    const float* W2  = (const float*)d_in[4];
    const float* b2  = (const float*)d_in[5];
    float* out = (float*)d_out;

    cudaFuncSetAttribute(fused_joint_kernel,
                         cudaFuncAttributeMaxDynamicSharedMemorySize, SMEM_TOTAL);

    prep_kernel<<<1024 + 640, 256>>>(enc, dec, W1, b1, W2);
    fused_joint_kernel<<<kMRows / 128, 512, SMEM_TOTAL>>>(b2, out);
}